// round 16
// baseline (speedup 1.0000x reference)
#include <cuda_runtime.h>
#include <cuda_fp16.h>
#include <cstdint>

// Problem constants (fixed by the reference)
#define NN 50000
#define NE 800000
#define F_IN 256
#define F_HID 128
#define F_OUT 64

// ---------------- scratch (__device__ globals; no allocation) ----------------
__device__ __half g_h1s[(size_t)NN * F_HID];  // x@W1 (unscaled), fp16
__device__ float  g_h1 [(size_t)NN * F_HID];  // relu(agg*rs_in + b1), fp32 (gemm2 A)
__device__ __half g_h2s[(size_t)NN * F_OUT];  // (h1@W2)*rs_out, fp16
__device__ int    g_deg_out[NN];
__device__ int    g_deg_in[NN];
__device__ float  g_rs_out[NN];
__device__ int    g_row_start[NN];
__device__ int    g_slot[NE];                 // per-edge unique slot within dst node
__device__ int    g_csr[NE];                  // src ids grouped by dst
__device__ int    g_total;

// ---------------- streams/events for fork-join (created once at load) ----------------
struct ForkJoin {
    cudaStream_t s2;
    cudaEvent_t  evFork, evJoin;
    ForkJoin() {
        cudaStreamCreateWithFlags(&s2, cudaStreamNonBlocking);
        cudaEventCreateWithFlags(&evFork, cudaEventDisableTiming);
        cudaEventCreateWithFlags(&evJoin, cudaEventDisableTiming);
    }
};
static ForkJoin g_fj;

// ---------------- zero counters (int4 vectorized) ----------------
__global__ void zero_counts_kernel() {
    int i = blockIdx.x * blockDim.x + threadIdx.x;
    const int DEG_V4 = NN / 4;   // 12500
    if (i < DEG_V4) {
        reinterpret_cast<int4*>(g_deg_out)[i] = make_int4(0, 0, 0, 0);
        reinterpret_cast<int4*>(g_deg_in)[i]  = make_int4(0, 0, 0, 0);
    }
    if (i == 0) g_total = 0;
}

// ---------------- degree counting + slot assignment (4 edges/thread) ----------------
__global__ void degree_kernel(const int* __restrict__ src, const int* __restrict__ dst) {
    int t = blockIdx.x * blockDim.x + threadIdx.x;
    if (t >= NE / 4) return;
    int4 s4 = reinterpret_cast<const int4*>(src)[t];
    int4 d4 = reinterpret_cast<const int4*>(dst)[t];
    atomicAdd(&g_deg_out[s4.x], 1);
    atomicAdd(&g_deg_out[s4.y], 1);
    atomicAdd(&g_deg_out[s4.z], 1);
    atomicAdd(&g_deg_out[s4.w], 1);
    int4 sl;
    sl.x = atomicAdd(&g_deg_in[d4.x], 1);
    sl.y = atomicAdd(&g_deg_in[d4.y], 1);
    sl.z = atomicAdd(&g_deg_in[d4.z], 1);
    sl.w = atomicAdd(&g_deg_in[d4.w], 1);
    reinterpret_cast<int4*>(g_slot)[t] = sl;
}

// ---------------- offsets (warp-aggregated) + rs_out ----------------
__global__ void offsets_kernel() {
    int i = blockIdx.x * blockDim.x + threadIdx.x;
    int lane = threadIdx.x & 31;
    int v = (i < NN) ? g_deg_in[i] : 0;
    int s = v;
#pragma unroll
    for (int off = 1; off < 32; off <<= 1) {
        int t = __shfl_up_sync(0xFFFFFFFFu, s, off);
        if (lane >= off) s += t;
    }
    int total = __shfl_sync(0xFFFFFFFFu, s, 31);
    int base = 0;
    if (lane == 0) base = atomicAdd(&g_total, total);
    base = __shfl_sync(0xFFFFFFFFu, base, 0);
    if (i < NN) {
        g_row_start[i] = base + s - v;
        g_rs_out[i]    = rsqrtf((float)max(g_deg_out[i], 1));
    }
}

// ---------------- binning: atomic-free streaming scatter (4 edges/thread) ----------------
__global__ void bin_kernel(const int* __restrict__ src, const int* __restrict__ dst) {
    int t = blockIdx.x * blockDim.x + threadIdx.x;
    if (t >= NE / 4) return;
    int4 s4 = reinterpret_cast<const int4*>(src)[t];
    int4 d4 = reinterpret_cast<const int4*>(dst)[t];
    int4 sl = reinterpret_cast<const int4*>(g_slot)[t];
    g_csr[__ldg(&g_row_start[d4.x]) + sl.x] = s4.x;
    g_csr[__ldg(&g_row_start[d4.y]) + sl.y] = s4.y;
    g_csr[__ldg(&g_row_start[d4.z]) + sl.z] = s4.z;
    g_csr[__ldg(&g_row_start[d4.w]) + sl.w] = s4.w;
}

// ---------------- tf32 tensor-core helpers ----------------
__device__ __forceinline__ uint32_t f2tf32(float f) {
    uint32_t u;
    asm("cvt.rna.tf32.f32 %0, %1;" : "=r"(u) : "f"(f));
    return u;
}

__device__ __forceinline__ void mma_tf32(float* d, const uint32_t* a, const uint32_t* b) {
    asm volatile(
        "mma.sync.aligned.m16n8k8.row.col.f32.tf32.tf32.f32 "
        "{%0,%1,%2,%3}, {%4,%5,%6,%7}, {%8,%9}, {%0,%1,%2,%3};"
        : "+f"(d[0]), "+f"(d[1]), "+f"(d[2]), "+f"(d[3])
        : "r"(a[0]), "r"(a[1]), "r"(a[2]), "r"(a[3]), "r"(b[0]), "r"(b[1]));
}

// epilogue pair stores (fp32 or fp16 output)
__device__ __forceinline__ void store_pair(float* p, float a, float b) {
    *reinterpret_cast<float2*>(p) = make_float2(a, b);
}
__device__ __forceinline__ void store_pair(__half* p, float a, float b) {
    *reinterpret_cast<__half2*>(p) = __floats2half2_rn(a, b);
}

// ---------------- TF32 tensor GEMM (NPASS=1: plain tf32, NPASS=3: 3xTF32) ----------------
template <int BN, int WM, int WN, bool SCALE, int NPASS, typename OutT>
__device__ __forceinline__ void mma_gemm_core(
    const float* __restrict__ A, const float* __restrict__ B,
    OutT* __restrict__ C, const float* __restrict__ rs, int M, int K)
{
    constexpr int BM = 128, BK = 16;
    constexpr int WTM = BM / WM;
    constexpr int WTN = BN / WN;
    constexpr int MT = WTM / 16;
    constexpr int NT = WTN / 8;
    constexpr int NA = (BM * BK / 4) / 256;     // =2
    constexpr int NB = (BK * BN / 4) / 256;     // 2 (BN=128) or 1 (BN=64)
    constexpr int BNV = BN / 4;
    constexpr int PAD = 8;

    __shared__ float As[2][BK][BM + PAD];
    __shared__ float Bs[2][BK][BN + PAD];

    const int tid  = threadIdx.x;
    const int w    = tid >> 5;
    const int lane = tid & 31;
    const int g    = lane >> 2;
    const int tig  = lane & 3;
    const int wm   = w % WM;
    const int wn   = w / WM;
    const int rowBase = blockIdx.x * BM;

    float acc[MT][NT][4];
#pragma unroll
    for (int i = 0; i < MT; i++)
#pragma unroll
        for (int j = 0; j < NT; j++)
#pragma unroll
            for (int q = 0; q < 4; q++) acc[i][j][q] = 0.f;

    float4 aReg[NA], bReg[NB];

#pragma unroll
    for (int q = 0; q < NA; q++) {
        int f  = tid + q * 256;
        int m  = f >> 2;
        int kc = (f & 3) * 4;
        float4 av = make_float4(0.f, 0.f, 0.f, 0.f);
        int gr = rowBase + m;
        if (gr < M) av = *reinterpret_cast<const float4*>(A + (size_t)gr * K + kc);
        As[0][kc + 0][m] = av.x;
        As[0][kc + 1][m] = av.y;
        As[0][kc + 2][m] = av.z;
        As[0][kc + 3][m] = av.w;
    }
#pragma unroll
    for (int q = 0; q < NB; q++) {
        int f = tid + q * 256;
        int k = f / BNV;
        int c = (f % BNV) * 4;
        float4 bv = *reinterpret_cast<const float4*>(B + (size_t)k * BN + c);
        Bs[0][k][c + 0] = bv.x;
        Bs[0][k][c + 1] = bv.y;
        Bs[0][k][c + 2] = bv.z;
        Bs[0][k][c + 3] = bv.w;
    }
    __syncthreads();

    const int NTILES = K / BK;
    for (int kt = 0; kt < NTILES; kt++) {
        int cur = kt & 1;
        int nxt = cur ^ 1;
        if (kt + 1 < NTILES) {
            int kbase = (kt + 1) * BK;
#pragma unroll
            for (int q = 0; q < NA; q++) {
                int f  = tid + q * 256;
                int m  = f >> 2;
                int kc = (f & 3) * 4;
                aReg[q] = make_float4(0.f, 0.f, 0.f, 0.f);
                int gr = rowBase + m;
                if (gr < M)
                    aReg[q] = *reinterpret_cast<const float4*>(A + (size_t)gr * K + kbase + kc);
            }
#pragma unroll
            for (int q = 0; q < NB; q++) {
                int f = tid + q * 256;
                int k = f / BNV;
                int c = (f % BNV) * 4;
                bReg[q] = *reinterpret_cast<const float4*>(B + (size_t)(kbase + k) * BN + c);
            }
        }
#pragma unroll
        for (int kk = 0; kk < BK; kk += 8) {
            uint32_t bh[NT][2], bl[NT][2];
#pragma unroll
            for (int ni = 0; ni < NT; ni++) {
                int bc = wn * WTN + ni * 8 + g;
                float b0 = Bs[cur][kk + tig][bc];
                float b1 = Bs[cur][kk + tig + 4][bc];
                bh[ni][0] = f2tf32(b0);
                bh[ni][1] = f2tf32(b1);
                if (NPASS == 3) {
                    bl[ni][0] = f2tf32(b0 - __uint_as_float(bh[ni][0]));
                    bl[ni][1] = f2tf32(b1 - __uint_as_float(bh[ni][1]));
                }
            }
#pragma unroll
            for (int mi = 0; mi < MT; mi++) {
                int ar = wm * WTM + mi * 16 + g;
                float a0 = As[cur][kk + tig][ar];
                float a1 = As[cur][kk + tig][ar + 8];
                float a2 = As[cur][kk + tig + 4][ar];
                float a3 = As[cur][kk + tig + 4][ar + 8];
                uint32_t ah[4], al[4];
                ah[0] = f2tf32(a0);
                ah[1] = f2tf32(a1);
                ah[2] = f2tf32(a2);
                ah[3] = f2tf32(a3);
                if (NPASS == 3) {
                    al[0] = f2tf32(a0 - __uint_as_float(ah[0]));
                    al[1] = f2tf32(a1 - __uint_as_float(ah[1]));
                    al[2] = f2tf32(a2 - __uint_as_float(ah[2]));
                    al[3] = f2tf32(a3 - __uint_as_float(ah[3]));
                }
#pragma unroll
                for (int ni = 0; ni < NT; ni++) {
                    mma_tf32(acc[mi][ni], ah, bh[ni]);
                    if (NPASS == 3) {
                        mma_tf32(acc[mi][ni], al, bh[ni]);
                        mma_tf32(acc[mi][ni], ah, bl[ni]);
                    }
                }
            }
        }
        if (kt + 1 < NTILES) {
            __syncthreads();
#pragma unroll
            for (int q = 0; q < NA; q++) {
                int f  = tid + q * 256;
                int m  = f >> 2;
                int kc = (f & 3) * 4;
                As[nxt][kc + 0][m] = aReg[q].x;
                As[nxt][kc + 1][m] = aReg[q].y;
                As[nxt][kc + 2][m] = aReg[q].z;
                As[nxt][kc + 3][m] = aReg[q].w;
            }
#pragma unroll
            for (int q = 0; q < NB; q++) {
                int f = tid + q * 256;
                int k = f / BNV;
                int c = (f % BNV) * 4;
                Bs[nxt][k][c + 0] = bReg[q].x;
                Bs[nxt][k][c + 1] = bReg[q].y;
                Bs[nxt][k][c + 2] = bReg[q].z;
                Bs[nxt][k][c + 3] = bReg[q].w;
            }
            __syncthreads();
        }
    }

#pragma unroll
    for (int mi = 0; mi < MT; mi++) {
        int r0 = rowBase + wm * WTM + mi * 16 + g;
        int r1 = r0 + 8;
        float s0 = 1.f, s1 = 1.f;
        if (SCALE) {
            s0 = (r0 < M) ? rs[r0] : 0.f;
            s1 = (r1 < M) ? rs[r1] : 0.f;
        }
#pragma unroll
        for (int ni = 0; ni < NT; ni++) {
            int c = wn * WTN + ni * 8 + tig * 2;
            if (r0 < M)
                store_pair(C + (size_t)r0 * BN + c, acc[mi][ni][0] * s0, acc[mi][ni][1] * s0);
            if (r1 < M)
                store_pair(C + (size_t)r1 * BN + c, acc[mi][ni][2] * s1, acc[mi][ni][3] * s1);
        }
    }
}

// gemm1: 1xTF32
__global__ __launch_bounds__(256) void gemm1_kernel(const float* __restrict__ x,
                                                    const float* __restrict__ W1) {
    mma_gemm_core<F_HID, 2, 4, false, 1, __half>(x, W1, g_h1s, nullptr, NN, F_IN);
}

// gemm2: 1xTF32
__global__ __launch_bounds__(256) void gemm2_kernel(const float* __restrict__ W2) {
    mma_gemm_core<F_OUT, 4, 2, true, 1, __half>(g_h1, W2, g_h2s, g_rs_out, NN, F_HID);
}

// ---------------- gather128: warp per node, HALF-WARP per neighbor ----------------
__global__ void gather128_kernel(const float* __restrict__ b1) {
    int node = (blockIdx.x * blockDim.x + threadIdx.x) >> 5;
    int lane = threadIdx.x & 31;
    int half = lane >> 4;        // 0 or 1: which neighbor of the pair
    int sub  = lane & 15;        // feature group: halfs [sub*8, sub*8+8)
    if (node >= NN) return;
    int start = g_row_start[node];
    int deg   = g_deg_in[node];

    float acc[8];
#pragma unroll
    for (int i = 0; i < 8; i++) acc[i] = 0.f;

    for (int base = 0; base < deg; base += 32) {
        int e = base + lane;
        int   sid = 0;
        float rov = 0.f;
        if (e < deg) {
            sid = __ldg(&g_csr[start + e]);
            rov = __ldg(&g_rs_out[sid]);
        }
        int cnt = min(32, deg - base);
        for (int j = 0; j < cnt; j += 4) {
            int jA = j + half;
            int jB = j + 2 + half;
            int   sA = __shfl_sync(0xFFFFFFFFu, sid, jA);
            float rA = __shfl_sync(0xFFFFFFFFu, rov, jA);
            int   sB = __shfl_sync(0xFFFFFFFFu, sid, jB);
            float rB = __shfl_sync(0xFFFFFFFFu, rov, jB);
            uint4 uA = __ldg(reinterpret_cast<const uint4*>(&g_h1s[(size_t)sA * F_HID + sub * 8]));
            uint4 uB = __ldg(reinterpret_cast<const uint4*>(&g_h1s[(size_t)sB * F_HID + sub * 8]));
            float2 p0 = __half22float2(*reinterpret_cast<__half2*>(&uA.x));
            float2 p1 = __half22float2(*reinterpret_cast<__half2*>(&uA.y));
            float2 p2 = __half22float2(*reinterpret_cast<__half2*>(&uA.z));
            float2 p3 = __half22float2(*reinterpret_cast<__half2*>(&uA.w));
            acc[0] = fmaf(p0.x, rA, acc[0]); acc[1] = fmaf(p0.y, rA, acc[1]);
            acc[2] = fmaf(p1.x, rA, acc[2]); acc[3] = fmaf(p1.y, rA, acc[3]);
            acc[4] = fmaf(p2.x, rA, acc[4]); acc[5] = fmaf(p2.y, rA, acc[5]);
            acc[6] = fmaf(p3.x, rA, acc[6]); acc[7] = fmaf(p3.y, rA, acc[7]);
            float2 q0 = __half22float2(*reinterpret_cast<__half2*>(&uB.x));
            float2 q1 = __half22float2(*reinterpret_cast<__half2*>(&uB.y));
            float2 q2 = __half22float2(*reinterpret_cast<__half2*>(&uB.z));
            float2 q3 = __half22float2(*reinterpret_cast<__half2*>(&uB.w));
            acc[0] = fmaf(q0.x, rB, acc[0]); acc[1] = fmaf(q0.y, rB, acc[1]);
            acc[2] = fmaf(q1.x, rB, acc[2]); acc[3] = fmaf(q1.y, rB, acc[3]);
            acc[4] = fmaf(q2.x, rB, acc[4]); acc[5] = fmaf(q2.y, rB, acc[5]);
            acc[6] = fmaf(q3.x, rB, acc[6]); acc[7] = fmaf(q3.y, rB, acc[7]);
        }
    }

#pragma unroll
    for (int i = 0; i < 8; i++)
        acc[i] += __shfl_xor_sync(0xFFFFFFFFu, acc[i], 16);

    if (half == 0) {
        float rs = rsqrtf((float)max(deg, 1));
        float4 ba = *reinterpret_cast<const float4*>(&b1[sub * 8]);
        float4 bb = *reinterpret_cast<const float4*>(&b1[sub * 8 + 4]);
        float4 o0, o1;
        o0.x = fmaxf(fmaf(acc[0], rs, ba.x), 0.f);
        o0.y = fmaxf(fmaf(acc[1], rs, ba.y), 0.f);
        o0.z = fmaxf(fmaf(acc[2], rs, ba.z), 0.f);
        o0.w = fmaxf(fmaf(acc[3], rs, ba.w), 0.f);
        o1.x = fmaxf(fmaf(acc[4], rs, bb.x), 0.f);
        o1.y = fmaxf(fmaf(acc[5], rs, bb.y), 0.f);
        o1.z = fmaxf(fmaf(acc[6], rs, bb.z), 0.f);
        o1.w = fmaxf(fmaf(acc[7], rs, bb.w), 0.f);
        float* dstp = &g_h1[(size_t)node * F_HID + sub * 8];
        *reinterpret_cast<float4*>(dstp)     = o0;
        *reinterpret_cast<float4*>(dstp + 4) = o1;
    }
}

// ---------------- gather64: warp per node, QUARTER-WARP per neighbor ----------------
// Row = 64 halfs = 128B = 8 lanes x uint4(16B). Lane group grp = lane>>3 handles
// neighbor j+grp (4 neighbors in flight). Butterfly xor-reduce leaves every lane
// with the full per-feature sums; group 0 stores hidden; logits dot reduced over
// lanes 0-7.
__global__ void gather64_kernel(const float* __restrict__ b2, const float* __restrict__ Wf,
                                const float* __restrict__ bf,
                                float* __restrict__ logits, float* __restrict__ hidden) {
    int node = (blockIdx.x * blockDim.x + threadIdx.x) >> 5;
    int lane = threadIdx.x & 31;
    int grp  = lane >> 3;        // 0..3: which neighbor of the quad
    int sub  = lane & 7;         // feature group: halfs [sub*8, sub*8+8)
    if (node >= NN) return;
    int start = g_row_start[node];
    int deg   = g_deg_in[node];

    float acc[8];
#pragma unroll
    for (int i = 0; i < 8; i++) acc[i] = 0.f;

    for (int base = 0; base < deg; base += 32) {
        int e = base + lane;
        int sid = (e < deg) ? __ldg(&g_csr[start + e]) : 0;
        int cnt = min(32, deg - base);
        for (int j = 0; j < cnt; j += 4) {
            int jj = j + grp;
            int   s = __shfl_sync(0xFFFFFFFFu, sid, jj);
            bool  ok = (jj < cnt);
            uint4 u = __ldg(reinterpret_cast<const uint4*>(&g_h2s[(size_t)s * F_OUT + sub * 8]));
            float w = ok ? 1.f : 0.f;
            float2 p0 = __half22float2(*reinterpret_cast<__half2*>(&u.x));
            float2 p1 = __half22float2(*reinterpret_cast<__half2*>(&u.y));
            float2 p2 = __half22float2(*reinterpret_cast<__half2*>(&u.z));
            float2 p3 = __half22float2(*reinterpret_cast<__half2*>(&u.w));
            acc[0] = fmaf(p0.x, w, acc[0]); acc[1] = fmaf(p0.y, w, acc[1]);
            acc[2] = fmaf(p1.x, w, acc[2]); acc[3] = fmaf(p1.y, w, acc[3]);
            acc[4] = fmaf(p2.x, w, acc[4]); acc[5] = fmaf(p2.y, w, acc[5]);
            acc[6] = fmaf(p3.x, w, acc[6]); acc[7] = fmaf(p3.y, w, acc[7]);
        }
    }

    // butterfly reduce across the 4 groups: all lanes end with full sums
#pragma unroll
    for (int i = 0; i < 8; i++) {
        acc[i] += __shfl_xor_sync(0xFFFFFFFFu, acc[i], 8);
        acc[i] += __shfl_xor_sync(0xFFFFFFFFu, acc[i], 16);
    }

    float rs = rsqrtf((float)max(deg, 1));
    float h[8];
#pragma unroll
    for (int i = 0; i < 8; i++)
        h[i] = fmaf(acc[i], rs, __ldg(&b2[sub * 8 + i]));

    if (grp == 0) {
        float* dstp = &hidden[(size_t)node * F_OUT + sub * 8];
        *reinterpret_cast<float4*>(dstp)     = make_float4(h[0], h[1], h[2], h[3]);
        *reinterpret_cast<float4*>(dstp + 4) = make_float4(h[4], h[5], h[6], h[7]);
    }

    // logits: partial dot over this lane's 8 features (Wf [64,2] row-major)
    float p0 = 0.f, p1 = 0.f;
#pragma unroll
    for (int i = 0; i < 8; i++) {
        float2 wv = *reinterpret_cast<const float2*>(&Wf[(sub * 8 + i) * 2]);
        p0 = fmaf(h[i], wv.x, p0);
        p1 = fmaf(h[i], wv.y, p1);
    }
    // reduce over lanes 0..7 (all groups hold identical values; use group 0's lanes)
    p0 += __shfl_down_sync(0xFFFFFFFFu, p0, 4);
    p1 += __shfl_down_sync(0xFFFFFFFFu, p1, 4);
    p0 += __shfl_down_sync(0xFFFFFFFFu, p0, 2);
    p1 += __shfl_down_sync(0xFFFFFFFFu, p1, 2);
    p0 += __shfl_down_sync(0xFFFFFFFFu, p0, 1);
    p1 += __shfl_down_sync(0xFFFFFFFFu, p1, 1);
    if (lane == 0) {
        logits[(size_t)node * 2 + 0] = p0 + bf[0];
        logits[(size_t)node * 2 + 1] = p1 + bf[1];
    }
}

// ---------------- launcher ----------------
extern "C" void kernel_launch(void* const* d_in, const int* in_sizes, int n_in,
                              void* d_out, int out_size) {
    const float* x   = (const float*)d_in[0];
    const float* W1  = (const float*)d_in[1];
    const float* b1  = (const float*)d_in[2];
    const float* W2  = (const float*)d_in[3];
    const float* b2  = (const float*)d_in[4];
    const float* Wf  = (const float*)d_in[5];
    const float* bf  = (const float*)d_in[6];
    const int*   src = (const int*)d_in[7];
    const int*   dst = (const int*)d_in[8];

    float* out = (float*)d_out;
    float* logits = out;                       // [NN, 2]
    float* hidden = out + (size_t)NN * 2;      // [NN, 64]

    // ---- fork: side chain first (proven order), gemm1 on main ----
    cudaEventRecord(g_fj.evFork, 0);
    cudaStreamWaitEvent(g_fj.s2, g_fj.evFork, 0);

    // side stream: degrees + slots + CSR + rs_out
    zero_counts_kernel<<<(NN / 4 + 255) / 256, 256, 0, g_fj.s2>>>();
    degree_kernel<<<(NE / 4 + 255) / 256, 256, 0, g_fj.s2>>>(src, dst);
    offsets_kernel<<<(NN + 255) / 256, 256, 0, g_fj.s2>>>();
    bin_kernel<<<(NE / 4 + 255) / 256, 256, 0, g_fj.s2>>>(src, dst);
    cudaEventRecord(g_fj.evJoin, g_fj.s2);

    // main stream: layer-1 transform (no degree dependency)
    gemm1_kernel<<<(NN + 127) / 128, 256>>>(x, W1);

    // ---- join: gather needs CSR + degrees + rs_out + h1s ----
    cudaStreamWaitEvent(0, g_fj.evJoin, 0);

    gather128_kernel<<<(NN * 32 + 255) / 256, 256>>>(b1);

    // Layer 2 + head
    gemm2_kernel<<<(NN + 127) / 128, 256>>>(W2);
    gather64_kernel<<<(NN * 32 + 255) / 256, 256>>>(b2, Wf, bf, logits, hidden);
}

// round 17
// speedup vs baseline: 1.5457x; 1.5457x over previous
#include <cuda_runtime.h>
#include <cuda_fp16.h>
#include <cstdint>

// Problem constants (fixed by the reference)
#define NN 50000
#define NE 800000
#define F_IN 256
#define F_HID 128
#define F_OUT 64

// ---------------- scratch (__device__ globals; no allocation) ----------------
__device__ __half g_h1s[(size_t)NN * F_HID];  // x@W1 (unscaled), fp16
__device__ float  g_h1 [(size_t)NN * F_HID];  // relu(agg*rs_in + b1), fp32 (gemm2 A)
__device__ __half g_h2s[(size_t)NN * F_OUT];  // (h1@W2)*rs_out, fp16
__device__ int    g_deg_out[NN];
__device__ int    g_deg_in[NN];
__device__ float  g_rs_out[NN];
__device__ int    g_row_start[NN];
__device__ int    g_slot[NE];                 // per-edge unique slot within dst node
__device__ int    g_csr[NE];                  // src ids grouped by dst
__device__ int    g_total;

// ---------------- streams/events for fork-join (created once at load) ----------------
struct ForkJoin {
    cudaStream_t s2;
    cudaEvent_t  evFork, evJoin;
    ForkJoin() {
        cudaStreamCreateWithFlags(&s2, cudaStreamNonBlocking);
        cudaEventCreateWithFlags(&evFork, cudaEventDisableTiming);
        cudaEventCreateWithFlags(&evJoin, cudaEventDisableTiming);
    }
};
static ForkJoin g_fj;

// ---------------- zero counters (int4 vectorized) ----------------
__global__ void zero_counts_kernel() {
    int i = blockIdx.x * blockDim.x + threadIdx.x;
    const int DEG_V4 = NN / 4;   // 12500
    if (i < DEG_V4) {
        reinterpret_cast<int4*>(g_deg_out)[i] = make_int4(0, 0, 0, 0);
        reinterpret_cast<int4*>(g_deg_in)[i]  = make_int4(0, 0, 0, 0);
    }
    if (i == 0) g_total = 0;
}

// ---------------- degree counting + slot assignment (4 edges/thread) ----------------
__global__ void degree_kernel(const int* __restrict__ src, const int* __restrict__ dst) {
    int t = blockIdx.x * blockDim.x + threadIdx.x;
    if (t >= NE / 4) return;
    int4 s4 = reinterpret_cast<const int4*>(src)[t];
    int4 d4 = reinterpret_cast<const int4*>(dst)[t];
    atomicAdd(&g_deg_out[s4.x], 1);
    atomicAdd(&g_deg_out[s4.y], 1);
    atomicAdd(&g_deg_out[s4.z], 1);
    atomicAdd(&g_deg_out[s4.w], 1);
    int4 sl;
    sl.x = atomicAdd(&g_deg_in[d4.x], 1);
    sl.y = atomicAdd(&g_deg_in[d4.y], 1);
    sl.z = atomicAdd(&g_deg_in[d4.z], 1);
    sl.w = atomicAdd(&g_deg_in[d4.w], 1);
    reinterpret_cast<int4*>(g_slot)[t] = sl;
}

// ---------------- offsets (warp-aggregated) + rs_out ----------------
__global__ void offsets_kernel() {
    int i = blockIdx.x * blockDim.x + threadIdx.x;
    int lane = threadIdx.x & 31;
    int v = (i < NN) ? g_deg_in[i] : 0;
    int s = v;
#pragma unroll
    for (int off = 1; off < 32; off <<= 1) {
        int t = __shfl_up_sync(0xFFFFFFFFu, s, off);
        if (lane >= off) s += t;
    }
    int total = __shfl_sync(0xFFFFFFFFu, s, 31);
    int base = 0;
    if (lane == 0) base = atomicAdd(&g_total, total);
    base = __shfl_sync(0xFFFFFFFFu, base, 0);
    if (i < NN) {
        g_row_start[i] = base + s - v;
        g_rs_out[i]    = rsqrtf((float)max(g_deg_out[i], 1));
    }
}

// ---------------- binning: atomic-free streaming scatter (4 edges/thread) ----------------
__global__ void bin_kernel(const int* __restrict__ src, const int* __restrict__ dst) {
    int t = blockIdx.x * blockDim.x + threadIdx.x;
    if (t >= NE / 4) return;
    int4 s4 = reinterpret_cast<const int4*>(src)[t];
    int4 d4 = reinterpret_cast<const int4*>(dst)[t];
    int4 sl = reinterpret_cast<const int4*>(g_slot)[t];
    g_csr[__ldg(&g_row_start[d4.x]) + sl.x] = s4.x;
    g_csr[__ldg(&g_row_start[d4.y]) + sl.y] = s4.y;
    g_csr[__ldg(&g_row_start[d4.z]) + sl.z] = s4.z;
    g_csr[__ldg(&g_row_start[d4.w]) + sl.w] = s4.w;
}

// ---------------- tf32 tensor-core helpers ----------------
__device__ __forceinline__ uint32_t f2tf32(float f) {
    uint32_t u;
    asm("cvt.rna.tf32.f32 %0, %1;" : "=r"(u) : "f"(f));
    return u;
}

__device__ __forceinline__ void mma_tf32(float* d, const uint32_t* a, const uint32_t* b) {
    asm volatile(
        "mma.sync.aligned.m16n8k8.row.col.f32.tf32.tf32.f32 "
        "{%0,%1,%2,%3}, {%4,%5,%6,%7}, {%8,%9}, {%0,%1,%2,%3};"
        : "+f"(d[0]), "+f"(d[1]), "+f"(d[2]), "+f"(d[3])
        : "r"(a[0]), "r"(a[1]), "r"(a[2]), "r"(a[3]), "r"(b[0]), "r"(b[1]));
}

// epilogue pair stores (fp32 or fp16 output)
__device__ __forceinline__ void store_pair(float* p, float a, float b) {
    *reinterpret_cast<float2*>(p) = make_float2(a, b);
}
__device__ __forceinline__ void store_pair(__half* p, float a, float b) {
    *reinterpret_cast<__half2*>(p) = __floats2half2_rn(a, b);
}

// ---------------- TF32 tensor GEMM (NPASS=1: plain tf32, NPASS=3: 3xTF32) ----------------
template <int BN, int WM, int WN, bool SCALE, int NPASS, typename OutT>
__device__ __forceinline__ void mma_gemm_core(
    const float* __restrict__ A, const float* __restrict__ B,
    OutT* __restrict__ C, const float* __restrict__ rs, int M, int K)
{
    constexpr int BM = 128, BK = 16;
    constexpr int WTM = BM / WM;
    constexpr int WTN = BN / WN;
    constexpr int MT = WTM / 16;
    constexpr int NT = WTN / 8;
    constexpr int NA = (BM * BK / 4) / 256;     // =2
    constexpr int NB = (BK * BN / 4) / 256;     // 2 (BN=128) or 1 (BN=64)
    constexpr int BNV = BN / 4;
    constexpr int PAD = 8;

    __shared__ float As[2][BK][BM + PAD];
    __shared__ float Bs[2][BK][BN + PAD];

    const int tid  = threadIdx.x;
    const int w    = tid >> 5;
    const int lane = tid & 31;
    const int g    = lane >> 2;
    const int tig  = lane & 3;
    const int wm   = w % WM;
    const int wn   = w / WM;
    const int rowBase = blockIdx.x * BM;

    float acc[MT][NT][4];
#pragma unroll
    for (int i = 0; i < MT; i++)
#pragma unroll
        for (int j = 0; j < NT; j++)
#pragma unroll
            for (int q = 0; q < 4; q++) acc[i][j][q] = 0.f;

    float4 aReg[NA], bReg[NB];

#pragma unroll
    for (int q = 0; q < NA; q++) {
        int f  = tid + q * 256;
        int m  = f >> 2;
        int kc = (f & 3) * 4;
        float4 av = make_float4(0.f, 0.f, 0.f, 0.f);
        int gr = rowBase + m;
        if (gr < M) av = *reinterpret_cast<const float4*>(A + (size_t)gr * K + kc);
        As[0][kc + 0][m] = av.x;
        As[0][kc + 1][m] = av.y;
        As[0][kc + 2][m] = av.z;
        As[0][kc + 3][m] = av.w;
    }
#pragma unroll
    for (int q = 0; q < NB; q++) {
        int f = tid + q * 256;
        int k = f / BNV;
        int c = (f % BNV) * 4;
        float4 bv = *reinterpret_cast<const float4*>(B + (size_t)k * BN + c);
        Bs[0][k][c + 0] = bv.x;
        Bs[0][k][c + 1] = bv.y;
        Bs[0][k][c + 2] = bv.z;
        Bs[0][k][c + 3] = bv.w;
    }
    __syncthreads();

    const int NTILES = K / BK;
    for (int kt = 0; kt < NTILES; kt++) {
        int cur = kt & 1;
        int nxt = cur ^ 1;
        if (kt + 1 < NTILES) {
            int kbase = (kt + 1) * BK;
#pragma unroll
            for (int q = 0; q < NA; q++) {
                int f  = tid + q * 256;
                int m  = f >> 2;
                int kc = (f & 3) * 4;
                aReg[q] = make_float4(0.f, 0.f, 0.f, 0.f);
                int gr = rowBase + m;
                if (gr < M)
                    aReg[q] = *reinterpret_cast<const float4*>(A + (size_t)gr * K + kbase + kc);
            }
#pragma unroll
            for (int q = 0; q < NB; q++) {
                int f = tid + q * 256;
                int k = f / BNV;
                int c = (f % BNV) * 4;
                bReg[q] = *reinterpret_cast<const float4*>(B + (size_t)(kbase + k) * BN + c);
            }
        }
#pragma unroll
        for (int kk = 0; kk < BK; kk += 8) {
            uint32_t bh[NT][2], bl[NT][2];
#pragma unroll
            for (int ni = 0; ni < NT; ni++) {
                int bc = wn * WTN + ni * 8 + g;
                float b0 = Bs[cur][kk + tig][bc];
                float b1 = Bs[cur][kk + tig + 4][bc];
                bh[ni][0] = f2tf32(b0);
                bh[ni][1] = f2tf32(b1);
                if (NPASS == 3) {
                    bl[ni][0] = f2tf32(b0 - __uint_as_float(bh[ni][0]));
                    bl[ni][1] = f2tf32(b1 - __uint_as_float(bh[ni][1]));
                }
            }
#pragma unroll
            for (int mi = 0; mi < MT; mi++) {
                int ar = wm * WTM + mi * 16 + g;
                float a0 = As[cur][kk + tig][ar];
                float a1 = As[cur][kk + tig][ar + 8];
                float a2 = As[cur][kk + tig + 4][ar];
                float a3 = As[cur][kk + tig + 4][ar + 8];
                uint32_t ah[4], al[4];
                ah[0] = f2tf32(a0);
                ah[1] = f2tf32(a1);
                ah[2] = f2tf32(a2);
                ah[3] = f2tf32(a3);
                if (NPASS == 3) {
                    al[0] = f2tf32(a0 - __uint_as_float(ah[0]));
                    al[1] = f2tf32(a1 - __uint_as_float(ah[1]));
                    al[2] = f2tf32(a2 - __uint_as_float(ah[2]));
                    al[3] = f2tf32(a3 - __uint_as_float(ah[3]));
                }
#pragma unroll
                for (int ni = 0; ni < NT; ni++) {
                    mma_tf32(acc[mi][ni], ah, bh[ni]);
                    if (NPASS == 3) {
                        mma_tf32(acc[mi][ni], al, bh[ni]);
                        mma_tf32(acc[mi][ni], ah, bl[ni]);
                    }
                }
            }
        }
        if (kt + 1 < NTILES) {
            __syncthreads();
#pragma unroll
            for (int q = 0; q < NA; q++) {
                int f  = tid + q * 256;
                int m  = f >> 2;
                int kc = (f & 3) * 4;
                As[nxt][kc + 0][m] = aReg[q].x;
                As[nxt][kc + 1][m] = aReg[q].y;
                As[nxt][kc + 2][m] = aReg[q].z;
                As[nxt][kc + 3][m] = aReg[q].w;
            }
#pragma unroll
            for (int q = 0; q < NB; q++) {
                int f = tid + q * 256;
                int k = f / BNV;
                int c = (f % BNV) * 4;
                Bs[nxt][k][c + 0] = bReg[q].x;
                Bs[nxt][k][c + 1] = bReg[q].y;
                Bs[nxt][k][c + 2] = bReg[q].z;
                Bs[nxt][k][c + 3] = bReg[q].w;
            }
            __syncthreads();
        }
    }

#pragma unroll
    for (int mi = 0; mi < MT; mi++) {
        int r0 = rowBase + wm * WTM + mi * 16 + g;
        int r1 = r0 + 8;
        float s0 = 1.f, s1 = 1.f;
        if (SCALE) {
            s0 = (r0 < M) ? rs[r0] : 0.f;
            s1 = (r1 < M) ? rs[r1] : 0.f;
        }
#pragma unroll
        for (int ni = 0; ni < NT; ni++) {
            int c = wn * WTN + ni * 8 + tig * 2;
            if (r0 < M)
                store_pair(C + (size_t)r0 * BN + c, acc[mi][ni][0] * s0, acc[mi][ni][1] * s0);
            if (r1 < M)
                store_pair(C + (size_t)r1 * BN + c, acc[mi][ni][2] * s1, acc[mi][ni][3] * s1);
        }
    }
}

// gemm1: 1xTF32
__global__ __launch_bounds__(256) void gemm1_kernel(const float* __restrict__ x,
                                                    const float* __restrict__ W1) {
    mma_gemm_core<F_HID, 2, 4, false, 1, __half>(x, W1, g_h1s, nullptr, NN, F_IN);
}

// gemm2: 1xTF32
__global__ __launch_bounds__(256) void gemm2_kernel(const float* __restrict__ W2) {
    mma_gemm_core<F_OUT, 4, 2, true, 1, __half>(g_h1, W2, g_h2s, g_rs_out, NN, F_HID);
}

// ---------------- gather128: warp per node, HALF-WARP per neighbor, 8 neighbors/iter ----------------
// Row = 128 halfs = 256B = 16 lanes x uint4(16B). Lanes 0-15 handle even neighbors,
// lanes 16-31 odd neighbors; 4 independent uint4 loads per lane per iteration (MLP=4).
__global__ void gather128_kernel(const float* __restrict__ b1) {
    int node = (blockIdx.x * blockDim.x + threadIdx.x) >> 5;
    int lane = threadIdx.x & 31;
    int half = lane >> 4;        // 0 or 1
    int sub  = lane & 15;        // feature group: halfs [sub*8, sub*8+8)
    if (node >= NN) return;
    int start = g_row_start[node];
    int deg   = g_deg_in[node];

    float acc[8];
#pragma unroll
    for (int i = 0; i < 8; i++) acc[i] = 0.f;

    for (int base = 0; base < deg; base += 32) {
        int e = base + lane;
        int   sid = 0;
        float rov = 0.f;
        if (e < deg) {
            sid = __ldg(&g_csr[start + e]);
            rov = __ldg(&g_rs_out[sid]);
        }
        int cnt = min(32, deg - base);
        for (int j = 0; j < cnt; j += 8) {
            int jA = j + half;
            int jB = j + 2 + half;
            int jC = j + 4 + half;
            int jD = j + 6 + half;
            int   sA = __shfl_sync(0xFFFFFFFFu, sid, jA);
            float rA = __shfl_sync(0xFFFFFFFFu, rov, jA);
            int   sB = __shfl_sync(0xFFFFFFFFu, sid, jB);
            float rB = __shfl_sync(0xFFFFFFFFu, rov, jB);
            int   sC = __shfl_sync(0xFFFFFFFFu, sid, jC);
            float rC = __shfl_sync(0xFFFFFFFFu, rov, jC);
            int   sD = __shfl_sync(0xFFFFFFFFu, sid, jD);
            float rD = __shfl_sync(0xFFFFFFFFu, rov, jD);
            // invalid slots (jX >= cnt) carry rov=0 from their source lanes (e >= deg)
            uint4 uA = __ldg(reinterpret_cast<const uint4*>(&g_h1s[(size_t)sA * F_HID + sub * 8]));
            uint4 uB = __ldg(reinterpret_cast<const uint4*>(&g_h1s[(size_t)sB * F_HID + sub * 8]));
            uint4 uC = __ldg(reinterpret_cast<const uint4*>(&g_h1s[(size_t)sC * F_HID + sub * 8]));
            uint4 uD = __ldg(reinterpret_cast<const uint4*>(&g_h1s[(size_t)sD * F_HID + sub * 8]));
#define ACC_ROW(u, r)                                                         \
            {                                                                 \
                float2 t0 = __half22float2(*reinterpret_cast<__half2*>(&u.x));\
                float2 t1 = __half22float2(*reinterpret_cast<__half2*>(&u.y));\
                float2 t2 = __half22float2(*reinterpret_cast<__half2*>(&u.z));\
                float2 t3 = __half22float2(*reinterpret_cast<__half2*>(&u.w));\
                acc[0] = fmaf(t0.x, r, acc[0]); acc[1] = fmaf(t0.y, r, acc[1]);\
                acc[2] = fmaf(t1.x, r, acc[2]); acc[3] = fmaf(t1.y, r, acc[3]);\
                acc[4] = fmaf(t2.x, r, acc[4]); acc[5] = fmaf(t2.y, r, acc[5]);\
                acc[6] = fmaf(t3.x, r, acc[6]); acc[7] = fmaf(t3.y, r, acc[7]);\
            }
            ACC_ROW(uA, rA)
            ACC_ROW(uB, rB)
            ACC_ROW(uC, rC)
            ACC_ROW(uD, rD)
#undef ACC_ROW
        }
    }

#pragma unroll
    for (int i = 0; i < 8; i++)
        acc[i] += __shfl_xor_sync(0xFFFFFFFFu, acc[i], 16);

    if (half == 0) {
        float rs = rsqrtf((float)max(deg, 1));
        float4 ba = *reinterpret_cast<const float4*>(&b1[sub * 8]);
        float4 bb = *reinterpret_cast<const float4*>(&b1[sub * 8 + 4]);
        float4 o0, o1;
        o0.x = fmaxf(fmaf(acc[0], rs, ba.x), 0.f);
        o0.y = fmaxf(fmaf(acc[1], rs, ba.y), 0.f);
        o0.z = fmaxf(fmaf(acc[2], rs, ba.z), 0.f);
        o0.w = fmaxf(fmaf(acc[3], rs, ba.w), 0.f);
        o1.x = fmaxf(fmaf(acc[4], rs, bb.x), 0.f);
        o1.y = fmaxf(fmaf(acc[5], rs, bb.y), 0.f);
        o1.z = fmaxf(fmaf(acc[6], rs, bb.z), 0.f);
        o1.w = fmaxf(fmaf(acc[7], rs, bb.w), 0.f);
        float* dstp = &g_h1[(size_t)node * F_HID + sub * 8];
        *reinterpret_cast<float4*>(dstp)     = o0;
        *reinterpret_cast<float4*>(dstp + 4) = o1;
    }
}

// ---------------- gather64 (R15 proven version): warp per node, fp16 operands ----------------
__global__ void gather64_kernel(const float* __restrict__ b2, const float* __restrict__ Wf,
                                const float* __restrict__ bf,
                                float* __restrict__ logits, float* __restrict__ hidden) {
    int node = (blockIdx.x * blockDim.x + threadIdx.x) >> 5;
    int lane = threadIdx.x & 31;
    if (node >= NN) return;
    int start = g_row_start[node];
    int deg   = g_deg_in[node];
    float2 acc = make_float2(0.f, 0.f);
    for (int base = 0; base < deg; base += 32) {
        int e = base + lane;
        int sid = (e < deg) ? __ldg(&g_csr[start + e]) : 0;
        int cnt = min(32, deg - base);
        int j = 0;
        for (; j + 4 <= cnt; j += 4) {
            int s0 = __shfl_sync(0xFFFFFFFFu, sid, j);
            int s1 = __shfl_sync(0xFFFFFFFFu, sid, j + 1);
            int s2 = __shfl_sync(0xFFFFFFFFu, sid, j + 2);
            int s3 = __shfl_sync(0xFFFFFFFFu, sid, j + 3);
            float2 v0 = __half22float2(__ldg(reinterpret_cast<const __half2*>(&g_h2s[(size_t)s0 * F_OUT + lane * 2])));
            float2 v1 = __half22float2(__ldg(reinterpret_cast<const __half2*>(&g_h2s[(size_t)s1 * F_OUT + lane * 2])));
            float2 v2 = __half22float2(__ldg(reinterpret_cast<const __half2*>(&g_h2s[(size_t)s2 * F_OUT + lane * 2])));
            float2 v3 = __half22float2(__ldg(reinterpret_cast<const __half2*>(&g_h2s[(size_t)s3 * F_OUT + lane * 2])));
            acc.x += (v0.x + v1.x) + (v2.x + v3.x);
            acc.y += (v0.y + v1.y) + (v2.y + v3.y);
        }
        for (; j < cnt; j++) {
            int s = __shfl_sync(0xFFFFFFFFu, sid, j);
            float2 v = __half22float2(__ldg(reinterpret_cast<const __half2*>(&g_h2s[(size_t)s * F_OUT + lane * 2])));
            acc.x += v.x; acc.y += v.y;
        }
    }
    float rs = rsqrtf((float)max(deg, 1));
    float h0 = fmaf(acc.x, rs, b2[lane * 2]);
    float h1 = fmaf(acc.y, rs, b2[lane * 2 + 1]);
    *reinterpret_cast<float2*>(&hidden[(size_t)node * F_OUT + lane * 2]) = make_float2(h0, h1);

    float2 w0 = *reinterpret_cast<const float2*>(&Wf[(lane * 2) * 2]);
    float2 w1 = *reinterpret_cast<const float2*>(&Wf[(lane * 2 + 1) * 2]);
    float p0 = fmaf(h0, w0.x, h1 * w1.x);
    float p1 = fmaf(h0, w0.y, h1 * w1.y);
#pragma unroll
    for (int off = 16; off > 0; off >>= 1) {
        p0 += __shfl_down_sync(0xFFFFFFFFu, p0, off);
        p1 += __shfl_down_sync(0xFFFFFFFFu, p1, off);
    }
    if (lane == 0) {
        logits[(size_t)node * 2 + 0] = p0 + bf[0];
        logits[(size_t)node * 2 + 1] = p1 + bf[1];
    }
}

// ---------------- launcher ----------------
extern "C" void kernel_launch(void* const* d_in, const int* in_sizes, int n_in,
                              void* d_out, int out_size) {
    const float* x   = (const float*)d_in[0];
    const float* W1  = (const float*)d_in[1];
    const float* b1  = (const float*)d_in[2];
    const float* W2  = (const float*)d_in[3];
    const float* b2  = (const float*)d_in[4];
    const float* Wf  = (const float*)d_in[5];
    const float* bf  = (const float*)d_in[6];
    const int*   src = (const int*)d_in[7];
    const int*   dst = (const int*)d_in[8];

    float* out = (float*)d_out;
    float* logits = out;                       // [NN, 2]
    float* hidden = out + (size_t)NN * 2;      // [NN, 64]

    // ---- fork: side chain first (proven order), gemm1 on main ----
    cudaEventRecord(g_fj.evFork, 0);
    cudaStreamWaitEvent(g_fj.s2, g_fj.evFork, 0);

    // side stream: degrees + slots + CSR + rs_out
    zero_counts_kernel<<<(NN / 4 + 255) / 256, 256, 0, g_fj.s2>>>();
    degree_kernel<<<(NE / 4 + 255) / 256, 256, 0, g_fj.s2>>>(src, dst);
    offsets_kernel<<<(NN + 255) / 256, 256, 0, g_fj.s2>>>();
    bin_kernel<<<(NE / 4 + 255) / 256, 256, 0, g_fj.s2>>>(src, dst);
    cudaEventRecord(g_fj.evJoin, g_fj.s2);

    // main stream: layer-1 transform (no degree dependency)
    gemm1_kernel<<<(NN + 127) / 128, 256>>>(x, W1);

    // ---- join: gather needs CSR + degrees + rs_out + h1s ----
    cudaStreamWaitEvent(0, g_fj.evJoin, 0);

    gather128_kernel<<<(NN * 32 + 255) / 256, 256>>>(b1);

    // Layer 2 + head
    gemm2_kernel<<<(NN + 127) / 128, 256>>>(W2);
    gather64_kernel<<<(NN * 32 + 255) / 256, 256>>>(b2, Wf, bf, logits, hidden);
}